// round 1
// baseline (speedup 1.0000x reference)
#include <cuda_runtime.h>

// Problem constants (fixed shapes for this dataset entry)
#define S_   16
#define P_   32
#define B_   512          // S_*P_
#define H_   64
#define E_   64
#define D1_  8192
#define BOT_ 1024
#define RTOT (S_*P_*P_)   // 16384 rows of the (s,a,b) GEMM

// Scratch (static __device__ arrays: allocation-free per harness rules)
__device__ float g_G[B_ * D1_];   // G[ped, d] = concat(b_sp, h[ped]) @ W1 + b1   (16 MB)
__device__ float g_M[2 * D1_];    // M[i, d]   = W_sp[i,:] @ W1[:64, d]

// ---------------- packed fp32 helpers (FFMA2 via PTX) ----------------
__device__ __forceinline__ unsigned long long pack2(float x, float y) {
    unsigned long long r;
    asm("mov.b64 %0, {%1, %2};" : "=l"(r) : "f"(x), "f"(y));
    return r;
}
__device__ __forceinline__ void unpack2(unsigned long long v, float& x, float& y) {
    asm("mov.b64 {%0, %1}, %2;" : "=f"(x), "=f"(y) : "l"(v));
}
__device__ __forceinline__ void ffma2(unsigned long long& d, unsigned long long a, unsigned long long b) {
    asm("fma.rn.f32x2 %0, %1, %2, %0;" : "+l"(d) : "l"(a), "l"(b));
}

// ---------------- Kernel A2: M = W_sp @ W1[:64, :]  (2 x 8192) ----------------
__global__ __launch_bounds__(256) void kern_M(const float* __restrict__ Wsp,
                                              const float* __restrict__ W1) {
    int d = blockIdx.x * 256 + threadIdx.x;
    float m0 = 0.f, m1 = 0.f;
    #pragma unroll 8
    for (int j = 0; j < 64; j++) {
        float w = W1[j * D1_ + d];
        m0 = fmaf(Wsp[j],      w, m0);
        m1 = fmaf(Wsp[64 + j], w, m1);
    }
    g_M[d]        = m0;
    g_M[D1_ + d]  = m1;
}

// ------------- Kernel A1: G = concat(b_sp, h) @ W1 + b1  (512 x 8192) -------------
// grid (D1_/256, B_/8), 256 threads. Each block: 8 rows x 256 cols, K=128.
__global__ __launch_bounds__(256) void kern_G(const float* __restrict__ h,
                                              const float* __restrict__ b_sp,
                                              const float* __restrict__ W1,
                                              const float* __restrict__ b1) {
    __shared__ float xs[8][128];
    const int tid  = threadIdx.x;
    const int col  = blockIdx.x * 256 + tid;
    const int row0 = blockIdx.y * 8;

    for (int e = tid; e < 8 * 128; e += 256) {
        int rr = e >> 7, j = e & 127;
        xs[rr][j] = (j < 64) ? b_sp[j] : h[(row0 + rr) * H_ + (j - 64)];
    }
    __syncthreads();

    float acc[8];
    float bb = b1[col];
    #pragma unroll
    for (int r = 0; r < 8; r++) acc[r] = bb;

    #pragma unroll 4
    for (int k = 0; k < 128; k++) {
        float w = W1[k * D1_ + col];
        #pragma unroll
        for (int r = 0; r < 8; r++) acc[r] = fmaf(xs[r][k], w, acc[r]);
    }
    #pragma unroll
    for (int r = 0; r < 8; r++) g_G[(row0 + r) * D1_ + col] = acc[r];
}

// ---------------- Kernel B: fused A-construction + GEMM2 + relu + max-pool ----------------
// C[r, n] = sum_k relu(rx[r]*M[0,k] + ry[r]*M[1,k] + G[g(r),k]) * W2[k,n]
// then out[ped, n] = relu(max_b C + b2[n]),  r = s*1024 + a*32 + b, ped = r/32.
// Tile: BM=128 (4 a's x 32 b's, one scene), BN=128, BK=16, 256 threads, 8x8 microtile.
__global__ __launch_bounds__(256, 2) void kern_main(const float* __restrict__ end_pos,
                                                    const float* __restrict__ W2,
                                                    const float* __restrict__ b2,
                                                    float* __restrict__ out) {
    __shared__ float As[16][128];
    __shared__ float Bs[16][128];
    __shared__ float Gs[16][32];
    __shared__ float Ms[2][16];
    __shared__ float rxs[128], rys[128];
    __shared__ float red[16][16][8];

    const int tid = threadIdx.x;
    const int tx  = tid & 15;        // col group
    const int ty  = tid >> 4;        // row group
    const int n0  = blockIdx.x * 128;
    const int r0  = blockIdx.y * 128;
    const int s   = r0 >> 10;        // scene (1024 rows per scene; tile never crosses scenes)
    const int pedbase = s * P_;

    // Per-row relative positions (NB=2 -> half=1: clip to [-1,1], /1)
    if (tid < 128) {
        int r = r0 + tid;
        int a = (r >> 5) & 31;
        int b = r & 31;
        float pax = end_pos[(pedbase + a) * 2 + 0], pay = end_pos[(pedbase + a) * 2 + 1];
        float pbx = end_pos[(pedbase + b) * 2 + 0], pby = end_pos[(pedbase + b) * 2 + 1];
        rxs[tid] = fminf(fmaxf(pbx - pax, -1.f), 1.f);
        rys[tid] = fminf(fmaxf(pby - pay, -1.f), 1.f);
    }

    unsigned long long c[8][4];
    #pragma unroll
    for (int i = 0; i < 8; i++)
        #pragma unroll
        for (int j = 0; j < 4; j++) c[i][j] = 0ull;

    const int le = tid * 8;
    const int lk = le >> 7;      // k row (0..15) for tile loads / expansion
    const int lm = le & 127;     // m or n offset (multiple of 8)

    for (int kt = 0; kt < D1_ / 16; kt++) {
        const int k0 = kt * 16;
        __syncthreads();   // previous compute done; safe to overwrite tiles

        // Load B tile: W2[k0+lk, n0+lm .. +7]
        {
            const float* src = W2 + (k0 + lk) * BOT_ + n0 + lm;
            float4 w0 = *(const float4*)(src);
            float4 w1 = *(const float4*)(src + 4);
            *(float4*)&Bs[lk][lm]     = w0;
            *(float4*)&Bs[lk][lm + 4] = w1;
        }
        // Stage distinct G values (32 b x 16 k) and M slice
        if (tid < 128) {
            int b  = tid >> 2;
            int kq = (tid & 3) * 4;
            float4 g = *(const float4*)(g_G + (pedbase + b) * D1_ + k0 + kq);
            Gs[kq + 0][b] = g.x; Gs[kq + 1][b] = g.y;
            Gs[kq + 2][b] = g.z; Gs[kq + 3][b] = g.w;
        } else if (tid < 160) {
            int t = tid - 128;
            Ms[t >> 4][t & 15] = g_M[(t >> 4) * D1_ + k0 + (t & 15)];
        }
        __syncthreads();

        // Expand A tile: As[k][m] = relu(rx*M0 + ry*M1 + G)
        {
            const float m0 = Ms[0][lk], m1 = Ms[1][lk];
            float v[8];
            #pragma unroll
            for (int q = 0; q < 8; q++) {
                int mm = lm + q;
                float t = fmaf(rxs[mm], m0, fmaf(rys[mm], m1, Gs[lk][mm & 31]));
                v[q] = fmaxf(t, 0.f);
            }
            *(float4*)&As[lk][lm]     = make_float4(v[0], v[1], v[2], v[3]);
            *(float4*)&As[lk][lm + 4] = make_float4(v[4], v[5], v[6], v[7]);
        }
        __syncthreads();

        // MMA: 8x8 microtile with packed FFMA2
        #pragma unroll
        for (int k = 0; k < 16; k++) {
            float4 a0 = *(const float4*)&As[k][ty * 8];
            float4 a1 = *(const float4*)&As[k][ty * 8 + 4];
            float4 b0 = *(const float4*)&Bs[k][tx * 8];
            float4 b1 = *(const float4*)&Bs[k][tx * 8 + 4];
            unsigned long long bb[4];
            bb[0] = pack2(b0.x, b0.y); bb[1] = pack2(b0.z, b0.w);
            bb[2] = pack2(b1.x, b1.y); bb[3] = pack2(b1.z, b1.w);
            float av[8] = {a0.x, a0.y, a0.z, a0.w, a1.x, a1.y, a1.z, a1.w};
            #pragma unroll
            for (int i = 0; i < 8; i++) {
                unsigned long long ap = pack2(av[i], av[i]);
                #pragma unroll
                for (int j = 0; j < 4; j++) ffma2(c[i][j], ap, bb[j]);
            }
        }
    }

    // Epilogue: max over the thread's 8 rows (all within one a-group since 8 | 32)
    float tmax[8];
    #pragma unroll
    for (int j = 0; j < 8; j++) tmax[j] = -1e30f;
    #pragma unroll
    for (int i = 0; i < 8; i++) {
        #pragma unroll
        for (int j = 0; j < 4; j++) {
            float x, y; unpack2(c[i][j], x, y);
            tmax[j * 2]     = fmaxf(tmax[j * 2], x);
            tmax[j * 2 + 1] = fmaxf(tmax[j * 2 + 1], y);
        }
    }
    #pragma unroll
    for (int j = 0; j < 8; j++) red[ty][tx][j] = tmax[j];
    __syncthreads();

    // Reduce across the 4 ty's sharing one a; then +b2, relu, store.
    if ((ty & 3) == 0) {
        const int g = ty >> 2;                 // local a index 0..3
        const int outrow = (r0 >> 5) + g;      // global ped = s*32 + a
        #pragma unroll
        for (int j = 0; j < 8; j++) {
            float m = fmaxf(fmaxf(red[ty][tx][j],     red[ty + 1][tx][j]),
                            fmaxf(red[ty + 2][tx][j], red[ty + 3][tx][j]));
            int n = n0 + tx * 8 + j;
            out[outrow * BOT_ + n] = fmaxf(m + b2[n], 0.f);
        }
    }
}

// ---------------------------------------------------------------------------
extern "C" void kernel_launch(void* const* d_in, const int* in_sizes, int n_in,
                              void* d_out, int out_size) {
    const float* h_states = (const float*)d_in[0];  // (1, 512, 64)
    const float* end_pos  = (const float*)d_in[1];  // (512, 2)
    // d_in[2] rel_pos: unused by reference
    // d_in[3] seq_start_end: scenes are fixed contiguous P=32 groups
    const float* W_sp = (const float*)d_in[4];      // (2, 64)
    const float* b_sp = (const float*)d_in[5];      // (64,)
    const float* W1   = (const float*)d_in[6];      // (128, 8192)
    const float* b1   = (const float*)d_in[7];      // (8192,)
    const float* W2   = (const float*)d_in[8];      // (8192, 1024)
    const float* b2   = (const float*)d_in[9];      // (1024,)
    float* out = (float*)d_out;                     // (512, 1024)

    kern_M<<<D1_ / 256, 256>>>(W_sp, W1);
    kern_G<<<dim3(D1_ / 256, B_ / 8), 256>>>(h_states, b_sp, W1, b1);
    kern_main<<<dim3(BOT_ / 128, RTOT / 128), 256>>>(end_pos, W2, b2, out);
}

// round 2
// speedup vs baseline: 1.0016x; 1.0016x over previous
#include <cuda_runtime.h>

// Problem constants (fixed shapes for this dataset entry)
#define S_   16
#define P_   32
#define B_   512          // S_*P_
#define H_   64
#define E_   64
#define D1_  8192
#define BOT_ 1024
#define RTOT (S_*P_*P_)   // 16384 rows of the (s,a,b) GEMM

// Scratch (static __device__ arrays: allocation-free per harness rules)
__device__ float g_G[B_ * D1_];   // G[ped, d] = concat(b_sp, h[ped]) @ W1 + b1   (16 MB)
__device__ float g_M[2 * D1_];    // M[i, d]   = W_sp[i,:] @ W1[:64, d]

// ---------------- packed fp32 helpers (FFMA2 via PTX) ----------------
__device__ __forceinline__ unsigned long long pack2(float x, float y) {
    unsigned long long r;
    asm("mov.b64 %0, {%1, %2};" : "=l"(r) : "f"(x), "f"(y));
    return r;
}
__device__ __forceinline__ void unpack2(unsigned long long v, float& x, float& y) {
    asm("mov.b64 {%0, %1}, %2;" : "=f"(x), "=f"(y) : "l"(v));
}
__device__ __forceinline__ void ffma2(unsigned long long& d, unsigned long long a, unsigned long long b) {
    asm("fma.rn.f32x2 %0, %1, %2, %0;" : "+l"(d) : "l"(a), "l"(b));
}

// ---------------- Kernel A2: M = W_sp @ W1[:64, :]  (2 x 8192) ----------------
__global__ __launch_bounds__(256) void kern_M(const float* __restrict__ Wsp,
                                              const float* __restrict__ W1) {
    int d = blockIdx.x * 256 + threadIdx.x;
    float m0 = 0.f, m1 = 0.f;
    #pragma unroll 8
    for (int j = 0; j < 64; j++) {
        float w = W1[j * D1_ + d];
        m0 = fmaf(Wsp[j],      w, m0);
        m1 = fmaf(Wsp[64 + j], w, m1);
    }
    g_M[d]        = m0;
    g_M[D1_ + d]  = m1;
}

// ------------- Kernel A1: G = concat(b_sp, h) @ W1 + b1  (512 x 8192) -------------
// grid (D1_/256, B_/8), 256 threads. Each block: 8 rows x 256 cols, K=128.
__global__ __launch_bounds__(256) void kern_G(const float* __restrict__ h,
                                              const float* __restrict__ b_sp,
                                              const float* __restrict__ W1,
                                              const float* __restrict__ b1) {
    __shared__ float xs[8][128];
    const int tid  = threadIdx.x;
    const int col  = blockIdx.x * 256 + tid;
    const int row0 = blockIdx.y * 8;

    for (int e = tid; e < 8 * 128; e += 256) {
        int rr = e >> 7, j = e & 127;
        xs[rr][j] = (j < 64) ? b_sp[j] : h[(row0 + rr) * H_ + (j - 64)];
    }
    __syncthreads();

    float acc[8];
    float bb = b1[col];
    #pragma unroll
    for (int r = 0; r < 8; r++) acc[r] = bb;

    #pragma unroll 4
    for (int k = 0; k < 128; k++) {
        float w = W1[k * D1_ + col];
        #pragma unroll
        for (int r = 0; r < 8; r++) acc[r] = fmaf(xs[r][k], w, acc[r]);
    }
    #pragma unroll
    for (int r = 0; r < 8; r++) g_G[(row0 + r) * D1_ + col] = acc[r];
}

// ---------------- Kernel B: fused A-construction + GEMM2 + relu + max-pool ----------------
// C[r, n] = sum_k relu(rx[r]*M[0,k] + ry[r]*M[1,k] + G[g(r),k]) * W2[k,n]
// then out[ped, n] = relu(max_b C + b2[n]),  r = s*1024 + a*32 + b, ped = r/32.
// Tile: BM=128 (4 a's x 32 b's, one scene), BN=128, BK=16, 256 threads, 8x8 microtile.
__global__ __launch_bounds__(256, 2) void kern_main(const float* __restrict__ end_pos,
                                                    const float* __restrict__ W2,
                                                    const float* __restrict__ b2,
                                                    float* __restrict__ out) {
    __shared__ float As[16][128];
    __shared__ float Bs[16][128];
    __shared__ float Gs[16][32];
    __shared__ float Ms[2][16];
    __shared__ float rxs[128], rys[128];
    __shared__ float red[16][16][8];

    const int tid = threadIdx.x;
    const int tx  = tid & 15;        // col group
    const int ty  = tid >> 4;        // row group
    const int n0  = blockIdx.x * 128;
    const int r0  = blockIdx.y * 128;
    const int s   = r0 >> 10;        // scene (1024 rows per scene; tile never crosses scenes)
    const int pedbase = s * P_;

    // Per-row relative positions (NB=2 -> half=1: clip to [-1,1], /1)
    if (tid < 128) {
        int r = r0 + tid;
        int a = (r >> 5) & 31;
        int b = r & 31;
        float pax = end_pos[(pedbase + a) * 2 + 0], pay = end_pos[(pedbase + a) * 2 + 1];
        float pbx = end_pos[(pedbase + b) * 2 + 0], pby = end_pos[(pedbase + b) * 2 + 1];
        rxs[tid] = fminf(fmaxf(pbx - pax, -1.f), 1.f);
        rys[tid] = fminf(fmaxf(pby - pay, -1.f), 1.f);
    }

    unsigned long long c[8][4];
    #pragma unroll
    for (int i = 0; i < 8; i++)
        #pragma unroll
        for (int j = 0; j < 4; j++) c[i][j] = 0ull;

    const int le = tid * 8;
    const int lk = le >> 7;      // k row (0..15) for tile loads / expansion
    const int lm = le & 127;     // m or n offset (multiple of 8)

    for (int kt = 0; kt < D1_ / 16; kt++) {
        const int k0 = kt * 16;
        __syncthreads();   // previous compute done; safe to overwrite tiles

        // Load B tile: W2[k0+lk, n0+lm .. +7]
        {
            const float* src = W2 + (k0 + lk) * BOT_ + n0 + lm;
            float4 w0 = *(const float4*)(src);
            float4 w1 = *(const float4*)(src + 4);
            *(float4*)&Bs[lk][lm]     = w0;
            *(float4*)&Bs[lk][lm + 4] = w1;
        }
        // Stage distinct G values (32 b x 16 k) and M slice
        if (tid < 128) {
            int b  = tid >> 2;
            int kq = (tid & 3) * 4;
            float4 g = *(const float4*)(g_G + (pedbase + b) * D1_ + k0 + kq);
            Gs[kq + 0][b] = g.x; Gs[kq + 1][b] = g.y;
            Gs[kq + 2][b] = g.z; Gs[kq + 3][b] = g.w;
        } else if (tid < 160) {
            int t = tid - 128;
            Ms[t >> 4][t & 15] = g_M[(t >> 4) * D1_ + k0 + (t & 15)];
        }
        __syncthreads();

        // Expand A tile: As[k][m] = relu(rx*M0 + ry*M1 + G)
        {
            const float m0 = Ms[0][lk], m1 = Ms[1][lk];
            float v[8];
            #pragma unroll
            for (int q = 0; q < 8; q++) {
                int mm = lm + q;
                float t = fmaf(rxs[mm], m0, fmaf(rys[mm], m1, Gs[lk][mm & 31]));
                v[q] = fmaxf(t, 0.f);
            }
            *(float4*)&As[lk][lm]     = make_float4(v[0], v[1], v[2], v[3]);
            *(float4*)&As[lk][lm + 4] = make_float4(v[4], v[5], v[6], v[7]);
        }
        __syncthreads();

        // MMA: 8x8 microtile with packed FFMA2
        #pragma unroll
        for (int k = 0; k < 16; k++) {
            float4 a0 = *(const float4*)&As[k][ty * 8];
            float4 a1 = *(const float4*)&As[k][ty * 8 + 4];
            float4 b0 = *(const float4*)&Bs[k][tx * 8];
            float4 b1 = *(const float4*)&Bs[k][tx * 8 + 4];
            unsigned long long bb[4];
            bb[0] = pack2(b0.x, b0.y); bb[1] = pack2(b0.z, b0.w);
            bb[2] = pack2(b1.x, b1.y); bb[3] = pack2(b1.z, b1.w);
            float av[8] = {a0.x, a0.y, a0.z, a0.w, a1.x, a1.y, a1.z, a1.w};
            #pragma unroll
            for (int i = 0; i < 8; i++) {
                unsigned long long ap = pack2(av[i], av[i]);
                #pragma unroll
                for (int j = 0; j < 4; j++) ffma2(c[i][j], ap, bb[j]);
            }
        }
    }

    // Epilogue: max over the thread's 8 rows (all within one a-group since 8 | 32)
    float tmax[8];
    #pragma unroll
    for (int j = 0; j < 8; j++) tmax[j] = -1e30f;
    #pragma unroll
    for (int i = 0; i < 8; i++) {
        #pragma unroll
        for (int j = 0; j < 4; j++) {
            float x, y; unpack2(c[i][j], x, y);
            tmax[j * 2]     = fmaxf(tmax[j * 2], x);
            tmax[j * 2 + 1] = fmaxf(tmax[j * 2 + 1], y);
        }
    }
    #pragma unroll
    for (int j = 0; j < 8; j++) red[ty][tx][j] = tmax[j];
    __syncthreads();

    // Reduce across the 4 ty's sharing one a; then +b2, relu, store.
    if ((ty & 3) == 0) {
        const int g = ty >> 2;                 // local a index 0..3
        const int outrow = (r0 >> 5) + g;      // global ped = s*32 + a
        #pragma unroll
        for (int j = 0; j < 8; j++) {
            float m = fmaxf(fmaxf(red[ty][tx][j],     red[ty + 1][tx][j]),
                            fmaxf(red[ty + 2][tx][j], red[ty + 3][tx][j]));
            int n = n0 + tx * 8 + j;
            out[outrow * BOT_ + n] = fmaxf(m + b2[n], 0.f);
        }
    }
}

// ---------------------------------------------------------------------------
extern "C" void kernel_launch(void* const* d_in, const int* in_sizes, int n_in,
                              void* d_out, int out_size) {
    const float* h_states = (const float*)d_in[0];  // (1, 512, 64)
    const float* end_pos  = (const float*)d_in[1];  // (512, 2)
    // d_in[2] rel_pos: unused by reference
    // d_in[3] seq_start_end: scenes are fixed contiguous P=32 groups
    const float* W_sp = (const float*)d_in[4];      // (2, 64)
    const float* b_sp = (const float*)d_in[5];      // (64,)
    const float* W1   = (const float*)d_in[6];      // (128, 8192)
    const float* b1   = (const float*)d_in[7];      // (8192,)
    const float* W2   = (const float*)d_in[8];      // (8192, 1024)
    const float* b2   = (const float*)d_in[9];      // (1024,)
    float* out = (float*)d_out;                     // (512, 1024)

    kern_M<<<D1_ / 256, 256>>>(W_sp, W1);
    kern_G<<<dim3(D1_ / 256, B_ / 8), 256>>>(h_states, b_sp, W1, b1);
    kern_main<<<dim3(BOT_ / 128, RTOT / 128), 256>>>(end_pos, W2, b2, out);
}

// round 4
// speedup vs baseline: 1.9588x; 1.9556x over previous
#include <cuda_runtime.h>
#include <cuda_bf16.h>
#include <cstdint>

// Problem constants
#define S_   16
#define P_   32
#define B_   512
#define H_   64
#define D1_  8192
#define BOT_ 1024
#define RTOT (S_*P_*P_)

// GEMM-2 tiling
#define BM   128
#define BN   128
#define BK   64
#define NCHUNK (D1_/BK)     // 128

// ---------------- device scratch (allocation-free) ----------------
__device__ __align__(256) float g_G[B_ * D1_];               // 16 MB fp32
__device__ __align__(256) float g_M[2 * D1_];
__device__ __align__(256) __nv_bfloat16 g_W2T_h[BOT_ * D1_]; // 16 MB  W2^T hi  [n][k]
__device__ __align__(256) __nv_bfloat16 g_W2T_l[BOT_ * D1_]; // 16 MB  W2^T lo  [n][k]

// ---------------- PTX helpers ----------------
__device__ __forceinline__ uint32_t smem_u32(const void* p) {
    uint32_t a;
    asm("{ .reg .u64 t; cvta.to.shared.u64 t, %1; cvt.u32.u64 %0, t; }" : "=r"(a) : "l"(p));
    return a;
}
#define SWZ(o) ((o) ^ (((o) >> 3) & 0x70))

__device__ __forceinline__ void mma16816(float* c, const uint32_t* a, const uint32_t* b) {
    asm volatile(
        "mma.sync.aligned.m16n8k16.row.col.f32.bf16.bf16.f32 "
        "{%0,%1,%2,%3}, {%4,%5,%6,%7}, {%8,%9}, {%0,%1,%2,%3};"
        : "+f"(c[0]), "+f"(c[1]), "+f"(c[2]), "+f"(c[3])
        : "r"(a[0]), "r"(a[1]), "r"(a[2]), "r"(a[3]), "r"(b[0]), "r"(b[1]));
}
__device__ __forceinline__ void ldsm4(uint32_t* r, uint32_t addr) {
    asm volatile("ldmatrix.sync.aligned.m8n8.x4.shared.b16 {%0,%1,%2,%3}, [%4];"
        : "=r"(r[0]), "=r"(r[1]), "=r"(r[2]), "=r"(r[3]) : "r"(addr));
}
#define CP16(dst, src) asm volatile("cp.async.ca.shared.global [%0], [%1], 16;" :: "r"(dst), "l"(src))
#define CP_COMMIT()    asm volatile("cp.async.commit_group;")
#define CP_WAIT0()     asm volatile("cp.async.wait_group 0;")

// ---------------- Prep kernels ----------------
__global__ __launch_bounds__(256) void kern_M(const float* __restrict__ Wsp,
                                              const float* __restrict__ W1) {
    int d = blockIdx.x * 256 + threadIdx.x;
    float m0 = 0.f, m1 = 0.f;
    #pragma unroll 8
    for (int j = 0; j < 64; j++) {
        float w = W1[j * D1_ + d];
        m0 = fmaf(Wsp[j],      w, m0);
        m1 = fmaf(Wsp[64 + j], w, m1);
    }
    g_M[d]       = m0;
    g_M[D1_ + d] = m1;
}

__global__ __launch_bounds__(256) void kern_G(const float* __restrict__ h,
                                              const float* __restrict__ b_sp,
                                              const float* __restrict__ W1,
                                              const float* __restrict__ b1) {
    __shared__ float xs[8][128];
    const int tid  = threadIdx.x;
    const int col  = blockIdx.x * 256 + tid;
    const int row0 = blockIdx.y * 8;
    for (int e = tid; e < 8 * 128; e += 256) {
        int rr = e >> 7, j = e & 127;
        xs[rr][j] = (j < 64) ? b_sp[j] : h[(row0 + rr) * H_ + (j - 64)];
    }
    __syncthreads();
    float acc[8];
    float bb = b1[col];
    #pragma unroll
    for (int r = 0; r < 8; r++) acc[r] = bb;
    #pragma unroll 4
    for (int k = 0; k < 128; k++) {
        float w = W1[k * D1_ + col];
        #pragma unroll
        for (int r = 0; r < 8; r++) acc[r] = fmaf(xs[r][k], w, acc[r]);
    }
    #pragma unroll
    for (int r = 0; r < 8; r++) g_G[(row0 + r) * D1_ + col] = acc[r];
}

// W2 [8192,1024] fp32 -> W2T hi/lo [1024,8192] bf16
__global__ __launch_bounds__(256) void kern_W2T(const float* __restrict__ W2) {
    __shared__ float tile[32][33];
    const int tx = threadIdx.x, ty = threadIdx.y;
    const int n0 = blockIdx.x * 32, k0 = blockIdx.y * 32;
    #pragma unroll
    for (int r = 0; r < 4; r++)
        tile[ty + r * 8][tx] = W2[(k0 + ty + r * 8) * BOT_ + n0 + tx];
    __syncthreads();
    #pragma unroll
    for (int r = 0; r < 4; r++) {
        float v = tile[tx][ty + r * 8];
        __nv_bfloat16 hi = __float2bfloat16(v);
        __nv_bfloat16 lo = __float2bfloat16(v - __bfloat162float(hi));
        int o = (n0 + ty + r * 8) * D1_ + k0 + tx;
        g_W2T_h[o] = hi;
        g_W2T_l[o] = lo;
    }
}

// ---------------- Main mma.sync kernel ----------------
// SMEM: rxs/rys (1KB), then 2 buffers x { Ah 16K | Al 16K | Bh 16K | Bl 16K }
#define OFF_TILE   1024
#define BUF_STRIDE 65536
#define SMEM_BYTES (OFF_TILE + 2 * BUF_STRIDE)   // 132096

// Build one chunk's tiles: cp.async for B (hi/lo) + ALU-built A (hi/lo split)
__device__ __forceinline__ void build_chunk(int k0, char* tileb, int t, int n0,
                                            const float* gp, float rx, float ry,
                                            uint32_t tb32) {
    // ---- B tiles via cp.async: 128 rows x 8 x 16B, hi + lo ----
    {
        uint32_t dH = tb32 + 32768, dL = tb32 + 49152;
        #pragma unroll
        for (int i = 0; i < 4; i++) {
            int seg = t + i * 256;
            int n = seg >> 3, ks = seg & 7;
            int sw = SWZ(n * 128 + ks * 16);
            const __nv_bfloat16* sH = g_W2T_h + (size_t)(n0 + n) * D1_ + k0 + ks * 8;
            const __nv_bfloat16* sL = g_W2T_l + (size_t)(n0 + n) * D1_ + k0 + ks * 8;
            CP16(dH + sw, sH);
            CP16(dL + sw, sL);
        }
    }
    // ---- A tiles: v = relu(rx*M0 + ry*M1 + G); split hi/lo bf16 ----
    {
        const int koffs = (t & 1) * 32;
        const int arow  = t >> 1;
        const int mk    = k0 + koffs;
        const int rowoff = arow * 128;
        const int rowxor = (arow & 7) << 4;
        char* pH = tileb;
        char* pL = tileb + 16384;
        #pragma unroll
        for (int j = 0; j < 8; j++) {
            float4 G  = *(const float4*)(gp + k0 + j * 4);
            float4 M0 = *(const float4*)(g_M + mk + j * 4);
            float4 M1 = *(const float4*)(g_M + D1_ + mk + j * 4);
            float v0 = fmaxf(fmaf(rx, M0.x, fmaf(ry, M1.x, G.x)), 0.f);
            float v1 = fmaxf(fmaf(rx, M0.y, fmaf(ry, M1.y, G.y)), 0.f);
            float v2 = fmaxf(fmaf(rx, M0.z, fmaf(ry, M1.z, G.z)), 0.f);
            float v3 = fmaxf(fmaf(rx, M0.w, fmaf(ry, M1.w, G.w)), 0.f);
            __nv_bfloat162 h01 = __floats2bfloat162_rn(v0, v1);
            __nv_bfloat162 h23 = __floats2bfloat162_rn(v2, v3);
            float2 f01 = __bfloat1622float2(h01);
            float2 f23 = __bfloat1622float2(h23);
            __nv_bfloat162 l01 = __floats2bfloat162_rn(v0 - f01.x, v1 - f01.y);
            __nv_bfloat162 l23 = __floats2bfloat162_rn(v2 - f23.x, v3 - f23.y);
            int kbyte = koffs * 2 + j * 8;
            int sw = rowoff + (kbyte ^ rowxor);
            *(uint2*)(pH + sw) = make_uint2(*(uint32_t*)&h01, *(uint32_t*)&h23);
            *(uint2*)(pL + sw) = make_uint2(*(uint32_t*)&l01, *(uint32_t*)&l23);
        }
    }
}

__global__ __launch_bounds__(256)
void kern_main_mma(const float* __restrict__ end_pos,
                   const float* __restrict__ b2,
                   float* __restrict__ out) {
    extern __shared__ __align__(1024) char smem[];
    const uint32_t sb = smem_u32(smem);
    const int t = threadIdx.x;
    const int lane = t & 31, wid = t >> 5;
    const int wm = wid >> 1, wn = wid & 1;
    const int n0 = blockIdx.x * BN;
    const int r0 = blockIdx.y * BM;
    const int pedbase = (r0 >> 10 << 5);   // scene * 32  (r0/1024*32)

    float* rxs = (float*)smem;
    float* rys = (float*)(smem + 512);

    // per-row clipped relative positions (NB=2 -> clip to [-1,1], /1)
    if (t < 128) {
        int a = ((r0 + t) >> 5) & 31;
        int b = t & 31;
        float pax = end_pos[(pedbase + a) * 2 + 0], pay = end_pos[(pedbase + a) * 2 + 1];
        float pbx = end_pos[(pedbase + b) * 2 + 0], pby = end_pos[(pedbase + b) * 2 + 1];
        rxs[t] = fminf(fmaxf(pbx - pax, -1.f), 1.f);
        rys[t] = fminf(fmaxf(pby - pay, -1.f), 1.f);
    }
    __syncthreads();

    // per-thread A-build constants
    const int arow = t >> 1;
    const float rx = rxs[arow], ry = rys[arow];
    const float* gp = g_G + (size_t)(pedbase + (arow & 31)) * D1_ + (t & 1) * 32;

    // ldmatrix lane address components
    // A: lanes 0-15 -> rows 0-15 (khalf 0), lanes 16-31 -> rows 0-15 (khalf 1)
    const int aRow    = wm * 32 + (lane & 15);            // + mt*16
    const int aKhalf  = lane >> 4;
    // B: n = (lane&7) + ((lane>>4)&1)*8, khalf = (lane>>3)&1  (+ pair p*16)
    const int bRow    = wn * 64 + (lane & 7) + ((lane >> 4) & 1) * 8;
    const int bKhalf  = (lane >> 3) & 1;

    float c[2][8][4];
    #pragma unroll
    for (int mt = 0; mt < 2; mt++)
        #pragma unroll
        for (int nt = 0; nt < 8; nt++)
            #pragma unroll
            for (int q = 0; q < 4; q++) c[mt][nt][q] = 0.f;

    // prologue: build chunk 0 into buffer 0
    build_chunk(0, smem + OFF_TILE, t, n0, gp, rx, ry, sb + OFF_TILE);
    CP_COMMIT(); CP_WAIT0();
    __syncthreads();

    for (int ch = 0; ch < NCHUNK; ch++) {
        const int buf = ch & 1;
        const uint32_t tb = sb + OFF_TILE + buf * BUF_STRIDE;

        if (ch + 1 < NCHUNK) {
            build_chunk((ch + 1) * BK, smem + OFF_TILE + (buf ^ 1) * BUF_STRIDE,
                        t, n0, gp, rx, ry, sb + OFF_TILE + (buf ^ 1) * BUF_STRIDE);
            CP_COMMIT();
        }

        // ---- MMAs on current buffer: 4 k16-steps x (2m x 8n x 3 terms) ----
        #pragma unroll
        for (int s = 0; s < 4; s++) {
            uint32_t ah[2][4], al[2][4], bh[4][4], bl[4][4];
            const int kbA = s * 32 + aKhalf * 16;
            #pragma unroll
            for (int mt = 0; mt < 2; mt++) {
                int row = aRow + mt * 16;
                uint32_t ad = tb + row * 128 + (kbA ^ ((row & 7) << 4));
                ldsm4(ah[mt], ad);
                ldsm4(al[mt], ad + 16384);
            }
            const int kbB = s * 32 + bKhalf * 16;
            #pragma unroll
            for (int p = 0; p < 4; p++) {
                int row = bRow + p * 16;
                uint32_t bd = tb + 32768 + row * 128 + (kbB ^ ((row & 7) << 4));
                ldsm4(bh[p], bd);
                ldsm4(bl[p], bd + 16384);
            }
            #pragma unroll
            for (int mt = 0; mt < 2; mt++)
                #pragma unroll
                for (int nt = 0; nt < 8; nt++) {
                    const uint32_t* BH = &bh[nt >> 1][(nt & 1) * 2];
                    const uint32_t* BL = &bl[nt >> 1][(nt & 1) * 2];
                    mma16816(c[mt][nt], ah[mt], BH);
                    mma16816(c[mt][nt], ah[mt], BL);
                    mma16816(c[mt][nt], al[mt], BH);
                }
        }

        if (ch + 1 < NCHUNK) {
            CP_WAIT0();
            __syncthreads();
        }
    }

    // ---- epilogue: max over the warp's 32 rows (= b), +b2, relu, store ----
    // rows: base = t/4 (+8, + mt*16); after 3 shfl_xor all lanes hold col maxes.
    const int ped = (r0 >> 5) + wm;
    const int cq = lane & 3;
    float* orow = out + (size_t)ped * BOT_ + n0 + wn * 64;
    const float* b2p = b2 + n0 + wn * 64;
    #pragma unroll
    for (int nt = 0; nt < 8; nt++) {
        #pragma unroll
        for (int j = 0; j < 2; j++) {
            float m = fmaxf(fmaxf(c[0][nt][j], c[0][nt][j + 2]),
                            fmaxf(c[1][nt][j], c[1][nt][j + 2]));
            m = fmaxf(m, __shfl_xor_sync(0xffffffffu, m, 4));
            m = fmaxf(m, __shfl_xor_sync(0xffffffffu, m, 8));
            m = fmaxf(m, __shfl_xor_sync(0xffffffffu, m, 16));
            if (lane < 4) {
                int n = nt * 8 + cq * 2 + j;
                orow[n] = fmaxf(m + b2p[n], 0.f);
            }
        }
    }
}

// ---------------------------------------------------------------------------
extern "C" void kernel_launch(void* const* d_in, const int* in_sizes, int n_in,
                              void* d_out, int out_size) {
    const float* h_states = (const float*)d_in[0];
    const float* end_pos  = (const float*)d_in[1];
    const float* W_sp = (const float*)d_in[4];
    const float* b_sp = (const float*)d_in[5];
    const float* W1   = (const float*)d_in[6];
    const float* b1   = (const float*)d_in[7];
    const float* W2   = (const float*)d_in[8];
    const float* b2   = (const float*)d_in[9];
    float* out = (float*)d_out;

    cudaFuncSetAttribute(kern_main_mma, cudaFuncAttributeMaxDynamicSharedMemorySize, SMEM_BYTES);

    kern_M<<<D1_ / 256, 256>>>(W_sp, W1);
    kern_G<<<dim3(D1_ / 256, B_ / 8), 256>>>(h_states, b_sp, W1, b1);
    kern_W2T<<<dim3(BOT_ / 32, D1_ / 32), dim3(32, 8)>>>(W2);
    kern_main_mma<<<dim3(BOT_ / BN, RTOT / BM), 256, SMEM_BYTES>>>(end_pos, b2, out);
}

// round 5
// speedup vs baseline: 2.5788x; 1.3165x over previous
#include <cuda_runtime.h>
#include <cuda_bf16.h>
#include <cstdint>

// Problem constants
#define S_   16
#define P_   32
#define B_   512
#define H_   64
#define D1_  8192
#define BOT_ 1024
#define RTOT (S_*P_*P_)

// GEMM-2 tiling
#define BM   128
#define BN   128
#define BK   32
#define NCHUNK (D1_/BK)     // 256

// ---------------- device scratch (allocation-free) ----------------
__device__ __align__(256) float g_G[B_ * D1_];               // 16 MB fp32
__device__ __align__(256) float g_M[2 * D1_];
__device__ __align__(256) __nv_bfloat16 g_W2T_h[BOT_ * D1_]; // 16 MB  W2^T hi  [n][k]
__device__ __align__(256) __nv_bfloat16 g_W2T_l[BOT_ * D1_]; // 16 MB  W2^T lo  [n][k]

// ---------------- PTX helpers ----------------
__device__ __forceinline__ uint32_t smem_u32(const void* p) {
    uint32_t a;
    asm("{ .reg .u64 t; cvta.to.shared.u64 t, %1; cvt.u32.u64 %0, t; }" : "=r"(a) : "l"(p));
    return a;
}
// 64-byte-row swizzle: XOR row bits [1:2] into 16B-column bits [4:5]
#define SWZ64(row, kbyte) ((row) * 64 + ((kbyte) ^ (((row) & 6) << 3)))

__device__ __forceinline__ void mma16816(float* c, const uint32_t* a, const uint32_t* b) {
    asm volatile(
        "mma.sync.aligned.m16n8k16.row.col.f32.bf16.bf16.f32 "
        "{%0,%1,%2,%3}, {%4,%5,%6,%7}, {%8,%9}, {%0,%1,%2,%3};"
        : "+f"(c[0]), "+f"(c[1]), "+f"(c[2]), "+f"(c[3])
        : "r"(a[0]), "r"(a[1]), "r"(a[2]), "r"(a[3]), "r"(b[0]), "r"(b[1]));
}
__device__ __forceinline__ void ldsm4(uint32_t* r, uint32_t addr) {
    asm volatile("ldmatrix.sync.aligned.m8n8.x4.shared.b16 {%0,%1,%2,%3}, [%4];"
        : "=r"(r[0]), "=r"(r[1]), "=r"(r[2]), "=r"(r[3]) : "r"(addr));
}
#define CP16(dst, src) asm volatile("cp.async.ca.shared.global [%0], [%1], 16;" :: "r"(dst), "l"(src))
#define CP_COMMIT()    asm volatile("cp.async.commit_group;")
#define CP_WAIT0()     asm volatile("cp.async.wait_group 0;")

// ---------------- Prep kernels ----------------
__global__ __launch_bounds__(256) void kern_M(const float* __restrict__ Wsp,
                                              const float* __restrict__ W1) {
    int d = blockIdx.x * 256 + threadIdx.x;
    float m0 = 0.f, m1 = 0.f;
    #pragma unroll 8
    for (int j = 0; j < 64; j++) {
        float w = W1[j * D1_ + d];
        m0 = fmaf(Wsp[j],      w, m0);
        m1 = fmaf(Wsp[64 + j], w, m1);
    }
    g_M[d]       = m0;
    g_M[D1_ + d] = m1;
}

__global__ __launch_bounds__(256) void kern_G(const float* __restrict__ h,
                                              const float* __restrict__ b_sp,
                                              const float* __restrict__ W1,
                                              const float* __restrict__ b1) {
    __shared__ float xs[8][128];
    const int tid  = threadIdx.x;
    const int col  = blockIdx.x * 256 + tid;
    const int row0 = blockIdx.y * 8;
    for (int e = tid; e < 8 * 128; e += 256) {
        int rr = e >> 7, j = e & 127;
        xs[rr][j] = (j < 64) ? b_sp[j] : h[(row0 + rr) * H_ + (j - 64)];
    }
    __syncthreads();
    float acc[8];
    float bb = b1[col];
    #pragma unroll
    for (int r = 0; r < 8; r++) acc[r] = bb;
    #pragma unroll 4
    for (int k = 0; k < 128; k++) {
        float w = W1[k * D1_ + col];
        #pragma unroll
        for (int r = 0; r < 8; r++) acc[r] = fmaf(xs[r][k], w, acc[r]);
    }
    #pragma unroll
    for (int r = 0; r < 8; r++) g_G[(row0 + r) * D1_ + col] = acc[r];
}

// W2 [8192,1024] fp32 -> W2T hi/lo [1024,8192] bf16
__global__ __launch_bounds__(256) void kern_W2T(const float* __restrict__ W2) {
    __shared__ float tile[32][33];
    const int tx = threadIdx.x, ty = threadIdx.y;
    const int n0 = blockIdx.x * 32, k0 = blockIdx.y * 32;
    #pragma unroll
    for (int r = 0; r < 4; r++)
        tile[ty + r * 8][tx] = W2[(k0 + ty + r * 8) * BOT_ + n0 + tx];
    __syncthreads();
    #pragma unroll
    for (int r = 0; r < 4; r++) {
        float v = tile[tx][ty + r * 8];
        __nv_bfloat16 hi = __float2bfloat16(v);
        __nv_bfloat16 lo = __float2bfloat16(v - __bfloat162float(hi));
        int o = (n0 + ty + r * 8) * D1_ + k0 + tx;
        g_W2T_h[o] = hi;
        g_W2T_l[o] = lo;
    }
}

// ---------------- Main mma.sync kernel ----------------
// SMEM: rxs/rys (1KB), then 2 buffers x { Ah 8K | Al 8K | Bh 8K | Bl 8K } = 66.5KB
#define OFF_TILE   1024
#define BUF_STRIDE 32768
#define A_LO   8192
#define B_HI   16384
#define B_LO   24576
#define SMEM_BYTES (OFF_TILE + 2 * BUF_STRIDE)   // 66560

// Build one chunk's tiles: cp.async for B (hi/lo) + ALU-built A (hi/lo split)
__device__ __forceinline__ void build_chunk(int k0, char* tileb, int t, int n0,
                                            const float* gp, float rx, float ry,
                                            uint32_t tb32) {
    // ---- B tiles via cp.async: 128 n-rows x 4 x 16B segs, hi + lo ----
    {
        uint32_t dH = tb32 + B_HI, dL = tb32 + B_LO;
        #pragma unroll
        for (int i = 0; i < 2; i++) {
            int idx = t + i * 256;
            int n = idx >> 2, seg = idx & 3;
            int sw = SWZ64(n, seg * 16);
            const __nv_bfloat16* sH = g_W2T_h + (size_t)(n0 + n) * D1_ + k0 + seg * 8;
            const __nv_bfloat16* sL = g_W2T_l + (size_t)(n0 + n) * D1_ + k0 + seg * 8;
            CP16(dH + sw, sH);
            CP16(dL + sw, sL);
        }
    }
    // ---- A tiles: v = relu(rx*M0 + ry*M1 + G); split hi/lo bf16 ----
    {
        const int koffs = (t & 1) * 16;          // 16 k-elements per thread
        const int arow  = t >> 1;
        const int mk    = k0 + koffs;
        char* pH = tileb;
        char* pL = tileb + A_LO;
        #pragma unroll
        for (int j = 0; j < 4; j++) {
            float4 G  = *(const float4*)(gp + k0 + j * 4);
            float4 M0 = *(const float4*)(g_M + mk + j * 4);
            float4 M1 = *(const float4*)(g_M + D1_ + mk + j * 4);
            float v0 = fmaxf(fmaf(rx, M0.x, fmaf(ry, M1.x, G.x)), 0.f);
            float v1 = fmaxf(fmaf(rx, M0.y, fmaf(ry, M1.y, G.y)), 0.f);
            float v2 = fmaxf(fmaf(rx, M0.z, fmaf(ry, M1.z, G.z)), 0.f);
            float v3 = fmaxf(fmaf(rx, M0.w, fmaf(ry, M1.w, G.w)), 0.f);
            __nv_bfloat162 h01 = __floats2bfloat162_rn(v0, v1);
            __nv_bfloat162 h23 = __floats2bfloat162_rn(v2, v3);
            float2 f01 = __bfloat1622float2(h01);
            float2 f23 = __bfloat1622float2(h23);
            __nv_bfloat162 l01 = __floats2bfloat162_rn(v0 - f01.x, v1 - f01.y);
            __nv_bfloat162 l23 = __floats2bfloat162_rn(v2 - f23.x, v3 - f23.y);
            int kbyte = koffs * 2 + j * 8;
            int sw = SWZ64(arow, kbyte);
            *(uint2*)(pH + sw) = make_uint2(*(uint32_t*)&h01, *(uint32_t*)&h23);
            *(uint2*)(pL + sw) = make_uint2(*(uint32_t*)&l01, *(uint32_t*)&l23);
        }
    }
}

__global__ __launch_bounds__(256, 2)
void kern_main_mma(const float* __restrict__ end_pos,
                   const float* __restrict__ b2,
                   float* __restrict__ out) {
    extern __shared__ __align__(1024) char smem[];
    const uint32_t sb = smem_u32(smem);
    const int t = threadIdx.x;
    const int lane = t & 31, wid = t >> 5;
    const int wm = wid >> 1, wn = wid & 1;
    const int n0 = blockIdx.x * BN;
    const int r0 = blockIdx.y * BM;
    const int pedbase = (r0 >> 10 << 5);   // scene * 32

    float* rxs = (float*)smem;
    float* rys = (float*)(smem + 512);

    // per-row clipped relative positions (NB=2 -> clip to [-1,1], /1)
    if (t < 128) {
        int a = ((r0 + t) >> 5) & 31;
        int b = t & 31;
        float pax = end_pos[(pedbase + a) * 2 + 0], pay = end_pos[(pedbase + a) * 2 + 1];
        float pbx = end_pos[(pedbase + b) * 2 + 0], pby = end_pos[(pedbase + b) * 2 + 1];
        rxs[t] = fminf(fmaxf(pbx - pax, -1.f), 1.f);
        rys[t] = fminf(fmaxf(pby - pay, -1.f), 1.f);
    }
    __syncthreads();

    // per-thread A-build constants
    const int arow = t >> 1;
    const float rx = rxs[arow], ry = rys[arow];
    const float* gp = g_G + (size_t)(pedbase + (arow & 31)) * D1_ + (t & 1) * 16;

    // ldmatrix lane address components
    const int aRow   = wm * 32 + (lane & 15);            // + mt*16
    const int aKhalf = lane >> 4;
    const int bRow   = wn * 64 + (lane & 7) + ((lane >> 4) & 1) * 8;
    const int bKhalf = (lane >> 3) & 1;

    float c[2][8][4];
    #pragma unroll
    for (int mt = 0; mt < 2; mt++)
        #pragma unroll
        for (int nt = 0; nt < 8; nt++)
            #pragma unroll
            for (int q = 0; q < 4; q++) c[mt][nt][q] = 0.f;

    // prologue: build chunk 0 into buffer 0
    build_chunk(0, smem + OFF_TILE, t, n0, gp, rx, ry, sb + OFF_TILE);
    CP_COMMIT(); CP_WAIT0();
    __syncthreads();

    for (int ch = 0; ch < NCHUNK; ch++) {
        const int buf = ch & 1;
        const uint32_t tb = sb + OFF_TILE + buf * BUF_STRIDE;

        if (ch + 1 < NCHUNK) {
            build_chunk((ch + 1) * BK, smem + OFF_TILE + (buf ^ 1) * BUF_STRIDE,
                        t, n0, gp, rx, ry, sb + OFF_TILE + (buf ^ 1) * BUF_STRIDE);
            CP_COMMIT();
        }

        // ---- MMAs on current buffer: 2 k16-steps x (2m x 8n x 3 terms) ----
        #pragma unroll
        for (int s = 0; s < 2; s++) {
            uint32_t ah[2][4], al[2][4], bh[4][4], bl[4][4];
            const int kbA = s * 32 + aKhalf * 16;
            #pragma unroll
            for (int mt = 0; mt < 2; mt++) {
                int row = aRow + mt * 16;
                uint32_t ad = tb + SWZ64(row, kbA);
                ldsm4(ah[mt], ad);
                ldsm4(al[mt], ad + A_LO);
            }
            const int kbB = s * 32 + bKhalf * 16;
            #pragma unroll
            for (int p = 0; p < 4; p++) {
                int row = bRow + p * 16;
                uint32_t bd = tb + B_HI + SWZ64(row, kbB);
                ldsm4(bh[p], bd);
                ldsm4(bl[p], bd + 8192);
            }
            #pragma unroll
            for (int mt = 0; mt < 2; mt++)
                #pragma unroll
                for (int nt = 0; nt < 8; nt++) {
                    const uint32_t* BH = &bh[nt >> 1][(nt & 1) * 2];
                    const uint32_t* BL = &bl[nt >> 1][(nt & 1) * 2];
                    mma16816(c[mt][nt], ah[mt], BH);
                    mma16816(c[mt][nt], ah[mt], BL);
                    mma16816(c[mt][nt], al[mt], BH);
                }
        }

        if (ch + 1 < NCHUNK) {
            CP_WAIT0();
            __syncthreads();
        }
    }

    // ---- epilogue: max over the warp's 32 rows (= b), +b2, relu, store ----
    const int ped = (r0 >> 5) + wm;
    const int cq = lane & 3;
    float* orow = out + (size_t)ped * BOT_ + n0 + wn * 64;
    const float* b2p = b2 + n0 + wn * 64;
    #pragma unroll
    for (int nt = 0; nt < 8; nt++) {
        #pragma unroll
        for (int j = 0; j < 2; j++) {
            float m = fmaxf(fmaxf(c[0][nt][j], c[0][nt][j + 2]),
                            fmaxf(c[1][nt][j], c[1][nt][j + 2]));
            m = fmaxf(m, __shfl_xor_sync(0xffffffffu, m, 4));
            m = fmaxf(m, __shfl_xor_sync(0xffffffffu, m, 8));
            m = fmaxf(m, __shfl_xor_sync(0xffffffffu, m, 16));
            if (lane < 4) {
                int n = nt * 8 + cq * 2 + j;
                orow[n] = fmaxf(m + b2p[n], 0.f);
            }
        }
    }
}

// ---------------------------------------------------------------------------
extern "C" void kernel_launch(void* const* d_in, const int* in_sizes, int n_in,
                              void* d_out, int out_size) {
    const float* h_states = (const float*)d_in[0];
    const float* end_pos  = (const float*)d_in[1];
    const float* W_sp = (const float*)d_in[4];
    const float* b_sp = (const float*)d_in[5];
    const float* W1   = (const float*)d_in[6];
    const float* b1   = (const float*)d_in[7];
    const float* W2   = (const float*)d_in[8];
    const float* b2   = (const float*)d_in[9];
    float* out = (float*)d_out;

    cudaFuncSetAttribute(kern_main_mma, cudaFuncAttributeMaxDynamicSharedMemorySize, SMEM_BYTES);

    kern_M<<<D1_ / 256, 256>>>(W_sp, W1);
    kern_G<<<dim3(D1_ / 256, B_ / 8), 256>>>(h_states, b_sp, W1, b1);
    kern_W2T<<<dim3(BOT_ / 32, D1_ / 32), dim3(32, 8)>>>(W2);
    kern_main_mma<<<dim3(BOT_ / BN, RTOT / BM), 256, SMEM_BYTES>>>(end_pos, b2, out);
}

// round 6
// speedup vs baseline: 2.8248x; 1.0954x over previous
#include <cuda_runtime.h>
#include <cuda_bf16.h>
#include <cstdint>

// Problem constants
#define S_   16
#define P_   32
#define B_   512
#define H_   64
#define D1_  8192
#define BOT_ 1024
#define RTOT (S_*P_*P_)

// GEMM-2 tiling
#define BM   128
#define BN   128
#define BK   32
#define NCHUNK (D1_/BK)     // 256

// ---------------- device scratch (allocation-free) ----------------
__device__ __align__(256) float g_G[B_ * D1_];               // 16 MB fp32
__device__ __align__(256) float g_M[2 * D1_];
__device__ __align__(256) __nv_bfloat16 g_W2T_h[BOT_ * D1_]; // W2^T hi  [n][k]
__device__ __align__(256) __nv_bfloat16 g_W2T_l[BOT_ * D1_]; // W2^T lo  [n][k]

// ---------------- PTX helpers ----------------
__device__ __forceinline__ uint32_t smem_u32(const void* p) {
    uint32_t a;
    asm("{ .reg .u64 t; cvta.to.shared.u64 t, %1; cvt.u32.u64 %0, t; }" : "=r"(a) : "l"(p));
    return a;
}
// 64-byte-row swizzle for B tiles
#define SWZ64(row, kbyte) ((row) * 64 + ((kbyte) ^ (((row) & 6) << 3)))

__device__ __forceinline__ void mma16816(float* c, const uint32_t* a, const uint32_t* b) {
    asm volatile(
        "mma.sync.aligned.m16n8k16.row.col.f32.bf16.bf16.f32 "
        "{%0,%1,%2,%3}, {%4,%5,%6,%7}, {%8,%9}, {%0,%1,%2,%3};"
        : "+f"(c[0]), "+f"(c[1]), "+f"(c[2]), "+f"(c[3])
        : "r"(a[0]), "r"(a[1]), "r"(a[2]), "r"(a[3]), "r"(b[0]), "r"(b[1]));
}
__device__ __forceinline__ void ldsm4(uint32_t* r, uint32_t addr) {
    asm volatile("ldmatrix.sync.aligned.m8n8.x4.shared.b16 {%0,%1,%2,%3}, [%4];"
        : "=r"(r[0]), "=r"(r[1]), "=r"(r[2]), "=r"(r[3]) : "r"(addr));
}
#define CP16(dst, src) asm volatile("cp.async.cg.shared.global [%0], [%1], 16;" :: "r"(dst), "l"(src))
#define CP_COMMIT()    asm volatile("cp.async.commit_group;")
#define CP_WAIT0()     asm volatile("cp.async.wait_group 0;")

__device__ __forceinline__ float2 lds_f2(uint32_t addr) {
    float2 v;
    asm volatile("ld.shared.v2.f32 {%0,%1}, [%2];" : "=f"(v.x), "=f"(v.y) : "r"(addr));
    return v;
}

// build one A-fragment register pair (hi/lo bf16 split of relu(rx*M0+ry*M1+G))
__device__ __forceinline__ void mk_frag(float2 m0, float2 m1, float2 g,
                                        float rx, float ry,
                                        uint32_t& hi, uint32_t& lo) {
    float v0 = fmaxf(fmaf(rx, m0.x, fmaf(ry, m1.x, g.x)), 0.f);
    float v1 = fmaxf(fmaf(rx, m0.y, fmaf(ry, m1.y, g.y)), 0.f);
    __nv_bfloat162 h = __floats2bfloat162_rn(v0, v1);
    uint32_t hb = *(uint32_t*)&h;
    float h0 = __uint_as_float(hb << 16);
    float h1 = __uint_as_float(hb & 0xffff0000u);
    __nv_bfloat162 l = __floats2bfloat162_rn(v0 - h0, v1 - h1);
    hi = hb;
    lo = *(uint32_t*)&l;
}

// ---------------- Prep kernels ----------------
__global__ __launch_bounds__(256) void kern_M(const float* __restrict__ Wsp,
                                              const float* __restrict__ W1) {
    int d = blockIdx.x * 256 + threadIdx.x;
    float m0 = 0.f, m1 = 0.f;
    #pragma unroll 8
    for (int j = 0; j < 64; j++) {
        float w = W1[j * D1_ + d];
        m0 = fmaf(Wsp[j],      w, m0);
        m1 = fmaf(Wsp[64 + j], w, m1);
    }
    g_M[d]       = m0;
    g_M[D1_ + d] = m1;
}

__global__ __launch_bounds__(256) void kern_G(const float* __restrict__ h,
                                              const float* __restrict__ b_sp,
                                              const float* __restrict__ W1,
                                              const float* __restrict__ b1) {
    __shared__ float xs[8][128];
    const int tid  = threadIdx.x;
    const int col  = blockIdx.x * 256 + tid;
    const int row0 = blockIdx.y * 8;
    for (int e = tid; e < 8 * 128; e += 256) {
        int rr = e >> 7, j = e & 127;
        xs[rr][j] = (j < 64) ? b_sp[j] : h[(row0 + rr) * H_ + (j - 64)];
    }
    __syncthreads();
    float acc[8];
    float bb = b1[col];
    #pragma unroll
    for (int r = 0; r < 8; r++) acc[r] = bb;
    #pragma unroll 4
    for (int k = 0; k < 128; k++) {
        float w = W1[k * D1_ + col];
        #pragma unroll
        for (int r = 0; r < 8; r++) acc[r] = fmaf(xs[r][k], w, acc[r]);
    }
    #pragma unroll
    for (int r = 0; r < 8; r++) g_G[(row0 + r) * D1_ + col] = acc[r];
}

__global__ __launch_bounds__(256) void kern_W2T(const float* __restrict__ W2) {
    __shared__ float tile[32][33];
    const int tx = threadIdx.x, ty = threadIdx.y;
    const int n0 = blockIdx.x * 32, k0 = blockIdx.y * 32;
    #pragma unroll
    for (int r = 0; r < 4; r++)
        tile[ty + r * 8][tx] = W2[(k0 + ty + r * 8) * BOT_ + n0 + tx];
    __syncthreads();
    #pragma unroll
    for (int r = 0; r < 4; r++) {
        float v = tile[tx][ty + r * 8];
        __nv_bfloat16 hi = __float2bfloat16(v);
        __nv_bfloat16 lo = __float2bfloat16(v - __bfloat162float(hi));
        int o = (n0 + ty + r * 8) * D1_ + k0 + tx;
        g_W2T_h[o] = hi;
        g_W2T_l[o] = lo;
    }
}

// ---------------- Main kernel ----------------
// SMEM per buffer: Bh 8K | Bl 8K | G 32x40 floats (5120B) | M 256B
#define B_LO_OFF  8192
#define G_OFF     16384
#define M_OFF     21504
#define BUF_STRIDE 22528
#define SMEM_BYTES (2 * BUF_STRIDE)   // 45056

// stage chunk k0 into buffer: B hi/lo tiles + G slice + M slice (all cp.async)
__device__ __forceinline__ void stage_chunk(int k0, uint32_t tb32, int t, int n0,
                                            int pedbase) {
    // B: 128 n-rows x 4 x 16B segs, hi + lo
    {
        uint32_t dH = tb32, dL = tb32 + B_LO_OFF;
        #pragma unroll
        for (int i = 0; i < 2; i++) {
            int idx = t + i * 256;
            int n = idx >> 2, seg = idx & 3;
            int sw = SWZ64(n, seg * 16);
            const __nv_bfloat16* sH = g_W2T_h + (size_t)(n0 + n) * D1_ + k0 + seg * 8;
            const __nv_bfloat16* sL = g_W2T_l + (size_t)(n0 + n) * D1_ + k0 + seg * 8;
            CP16(dH + sw, sH);
            CP16(dL + sw, sL);
        }
    }
    // G: 32 b-rows x 8 x 16B segs into padded rows (stride 160B)
    {
        int b = t >> 3, seg = t & 7;
        const float* src = g_G + (size_t)(pedbase + b) * D1_ + k0 + seg * 4;
        CP16(tb32 + G_OFF + b * 160 + seg * 16, src);
    }
    // M: 2 x 32 floats
    if (t < 16) {
        int half = t >> 3, seg = t & 7;
        const float* src = g_M + half * D1_ + k0 + seg * 4;
        CP16(tb32 + M_OFF + half * 128 + seg * 16, src);
    }
}

__global__ __launch_bounds__(256, 2)
void kern_main_mma(const float* __restrict__ end_pos,
                   const float* __restrict__ b2,
                   float* __restrict__ out) {
    extern __shared__ __align__(1024) char smem[];
    const uint32_t sb = smem_u32(smem);
    const int t = threadIdx.x;
    const int lane = t & 31, wid = t >> 5;
    const int wm = wid >> 1, wn = wid & 1;
    const int n0 = blockIdx.x * BN;
    const int r0 = blockIdx.y * BM;
    const int pedbase = (r0 >> 10) << 5;     // scene * 32

    // ---- per-thread rel-pos for the 4 A-fragment rows ----
    // a is warp-constant: a = 4*(by&7) + wm ; b rows: mt*16 + lane/4 (+8)
    const int a_idx = ((blockIdx.y & 7) << 2) + wm;
    const float pax = end_pos[(pedbase + a_idx) * 2 + 0];
    const float pay = end_pos[(pedbase + a_idx) * 2 + 1];
    const int g4 = lane >> 2;
    float rxv[4], ryv[4];   // [mt*2 + h]  (h: row, row+8)
    #pragma unroll
    for (int mt = 0; mt < 2; mt++)
        #pragma unroll
        for (int h = 0; h < 2; h++) {
            int b = mt * 16 + h * 8 + g4;
            float pbx = end_pos[(pedbase + b) * 2 + 0];
            float pby = end_pos[(pedbase + b) * 2 + 1];
            rxv[mt * 2 + h] = fminf(fmaxf(pbx - pax, -1.f), 1.f);
            ryv[mt * 2 + h] = fminf(fmaxf(pby - pay, -1.f), 1.f);
        }
    // G smem row offsets for the 4 b rows
    uint32_t gRow[4];
    #pragma unroll
    for (int mt = 0; mt < 2; mt++)
        #pragma unroll
        for (int h = 0; h < 2; h++)
            gRow[mt * 2 + h] = (mt * 16 + h * 8 + g4) * 160;

    // B ldmatrix lane addressing
    const int bRow   = wn * 64 + (lane & 7) + ((lane >> 4) & 1) * 8;
    const int bKhalf = (lane >> 3) & 1;
    const int kk0b   = (lane & 3) * 2;       // A-fragment k pair base (floats)

    float c[2][8][4];
    #pragma unroll
    for (int mt = 0; mt < 2; mt++)
        #pragma unroll
        for (int nt = 0; nt < 8; nt++)
            #pragma unroll
            for (int q = 0; q < 4; q++) c[mt][nt][q] = 0.f;

    // prologue
    stage_chunk(0, sb, t, n0, pedbase);
    CP_COMMIT(); CP_WAIT0();
    __syncthreads();

    for (int ch = 0; ch < NCHUNK; ch++) {
        const int buf = ch & 1;
        const uint32_t tb = sb + buf * BUF_STRIDE;

        if (ch + 1 < NCHUNK) {
            stage_chunk((ch + 1) * BK, sb + (buf ^ 1) * BUF_STRIDE, t, n0, pedbase);
            CP_COMMIT();
        }

        #pragma unroll
        for (int s = 0; s < 2; s++) {
            const int kk = s * 16 + kk0b;             // local k (floats) 0..31
            // M pairs (broadcast LDS)
            float2 m0a = lds_f2(tb + M_OFF + kk * 4);
            float2 m0b = lds_f2(tb + M_OFF + (kk + 8) * 4);
            float2 m1a = lds_f2(tb + M_OFF + 128 + kk * 4);
            float2 m1b = lds_f2(tb + M_OFF + 128 + (kk + 8) * 4);

            // B fragments
            uint32_t bh[4][4], bl[4][4];
            const int kbB = s * 32 + bKhalf * 16;
            #pragma unroll
            for (int p = 0; p < 4; p++) {
                int row = bRow + p * 16;
                uint32_t bd = tb + SWZ64(row, kbB);
                ldsm4(bh[p], bd);
                ldsm4(bl[p], bd + B_LO_OFF);
            }

            // A fragments built in registers
            uint32_t ah[2][4], al[2][4];
            #pragma unroll
            for (int mt = 0; mt < 2; mt++) {
                float2 g0a = lds_f2(tb + G_OFF + gRow[mt * 2 + 0] + kk * 4);
                float2 g1a = lds_f2(tb + G_OFF + gRow[mt * 2 + 1] + kk * 4);
                float2 g0b = lds_f2(tb + G_OFF + gRow[mt * 2 + 0] + (kk + 8) * 4);
                float2 g1b = lds_f2(tb + G_OFF + gRow[mt * 2 + 1] + (kk + 8) * 4);
                float rxa = rxv[mt * 2], rya = ryv[mt * 2];
                float rxb = rxv[mt * 2 + 1], ryb = ryv[mt * 2 + 1];
                mk_frag(m0a, m1a, g0a, rxa, rya, ah[mt][0], al[mt][0]);
                mk_frag(m0a, m1a, g1a, rxb, ryb, ah[mt][1], al[mt][1]);
                mk_frag(m0b, m1b, g0b, rxa, rya, ah[mt][2], al[mt][2]);
                mk_frag(m0b, m1b, g1b, rxb, ryb, ah[mt][3], al[mt][3]);
            }

            #pragma unroll
            for (int mt = 0; mt < 2; mt++)
                #pragma unroll
                for (int nt = 0; nt < 8; nt++) {
                    const uint32_t* BH = &bh[nt >> 1][(nt & 1) * 2];
                    const uint32_t* BL = &bl[nt >> 1][(nt & 1) * 2];
                    mma16816(c[mt][nt], ah[mt], BH);
                    mma16816(c[mt][nt], ah[mt], BL);
                    mma16816(c[mt][nt], al[mt], BH);
                }
        }

        if (ch + 1 < NCHUNK) {
            CP_WAIT0();
            __syncthreads();
        }
    }

    // ---- epilogue: max over warp's 32 rows (= b), +b2, relu, store ----
    const int ped = (r0 >> 5) + wm;
    const int cq = lane & 3;
    float* orow = out + (size_t)ped * BOT_ + n0 + wn * 64;
    const float* b2p = b2 + n0 + wn * 64;
    #pragma unroll
    for (int nt = 0; nt < 8; nt++) {
        #pragma unroll
        for (int j = 0; j < 2; j++) {
            float m = fmaxf(fmaxf(c[0][nt][j], c[0][nt][j + 2]),
                            fmaxf(c[1][nt][j], c[1][nt][j + 2]));
            m = fmaxf(m, __shfl_xor_sync(0xffffffffu, m, 4));
            m = fmaxf(m, __shfl_xor_sync(0xffffffffu, m, 8));
            m = fmaxf(m, __shfl_xor_sync(0xffffffffu, m, 16));
            if (lane < 4) {
                int n = nt * 8 + cq * 2 + j;
                orow[n] = fmaxf(m + b2p[n], 0.f);
            }
        }
    }
}

// ---------------------------------------------------------------------------
extern "C" void kernel_launch(void* const* d_in, const int* in_sizes, int n_in,
                              void* d_out, int out_size) {
    const float* h_states = (const float*)d_in[0];
    const float* end_pos  = (const float*)d_in[1];
    const float* W_sp = (const float*)d_in[4];
    const float* b_sp = (const float*)d_in[5];
    const float* W1   = (const float*)d_in[6];
    const float* b1   = (const float*)d_in[7];
    const float* W2   = (const float*)d_in[8];
    const float* b2   = (const float*)d_in[9];
    float* out = (float*)d_out;

    cudaFuncSetAttribute(kern_main_mma, cudaFuncAttributeMaxDynamicSharedMemorySize, SMEM_BYTES);

    kern_M<<<D1_ / 256, 256>>>(W_sp, W1);
    kern_G<<<dim3(D1_ / 256, B_ / 8), 256>>>(h_states, b_sp, W1, b1);
    kern_W2T<<<dim3(BOT_ / 32, D1_ / 32), dim3(32, 8)>>>(W2);
    kern_main_mma<<<dim3(BOT_ / BN, RTOT / BM), 256, SMEM_BYTES>>>(end_pos, b2, out);
}

// round 7
// speedup vs baseline: 3.0233x; 1.0703x over previous
#include <cuda_runtime.h>
#include <cuda_bf16.h>
#include <cstdint>

// Problem constants
#define S_   16
#define P_   32
#define B_   512
#define H_   64
#define D1_  8192
#define BOT_ 1024
#define RTOT (S_*P_*P_)

// GEMM-2 tiling
#define BM   64
#define BN   128
#define BK   64
#define NCHUNK (D1_/BK)     // 128

// ---------------- device scratch (allocation-free) ----------------
__device__ __align__(256) float g_G[B_ * D1_];               // 16 MB fp32
__device__ __align__(256) float g_M[2 * D1_];
__device__ __align__(256) __nv_bfloat16 g_W2T_h[BOT_ * D1_]; // W2^T hi  [n][k]
__device__ __align__(256) __nv_bfloat16 g_W2T_l[BOT_ * D1_]; // W2^T lo  [n][k]

// ---------------- PTX helpers ----------------
__device__ __forceinline__ uint32_t smem_u32(const void* p) {
    uint32_t a;
    asm("{ .reg .u64 t; cvta.to.shared.u64 t, %1; cvt.u32.u64 %0, t; }" : "=r"(a) : "l"(p));
    return a;
}
__device__ __forceinline__ void mma16816(float* c, const uint32_t* a, const uint32_t* b) {
    asm volatile(
        "mma.sync.aligned.m16n8k16.row.col.f32.bf16.bf16.f32 "
        "{%0,%1,%2,%3}, {%4,%5,%6,%7}, {%8,%9}, {%0,%1,%2,%3};"
        : "+f"(c[0]), "+f"(c[1]), "+f"(c[2]), "+f"(c[3])
        : "r"(a[0]), "r"(a[1]), "r"(a[2]), "r"(a[3]), "r"(b[0]), "r"(b[1]));
}
__device__ __forceinline__ void ldsm4(uint32_t* r, uint32_t addr) {
    asm volatile("ldmatrix.sync.aligned.m8n8.x4.shared.b16 {%0,%1,%2,%3}, [%4];"
        : "=r"(r[0]), "=r"(r[1]), "=r"(r[2]), "=r"(r[3]) : "r"(addr));
}
#define CP16(dst, src) asm volatile("cp.async.cg.shared.global [%0], [%1], 16;" :: "r"(dst), "l"(src))
#define CP_COMMIT()    asm volatile("cp.async.commit_group;")
#define CP_WAIT0()     asm volatile("cp.async.wait_group 0;")

__device__ __forceinline__ float2 lds_f2(uint32_t addr) {
    float2 v;
    asm volatile("ld.shared.v2.f32 {%0,%1}, [%2];" : "=f"(v.x), "=f"(v.y) : "r"(addr));
    return v;
}

// hi/lo bf16 split of relu(rx*M0 + ry*M1 + G)
__device__ __forceinline__ void mk_frag(float2 m0, float2 m1, float2 g,
                                        float rx, float ry,
                                        uint32_t& hi, uint32_t& lo) {
    float v0 = fmaxf(fmaf(rx, m0.x, fmaf(ry, m1.x, g.x)), 0.f);
    float v1 = fmaxf(fmaf(rx, m0.y, fmaf(ry, m1.y, g.y)), 0.f);
    __nv_bfloat162 h = __floats2bfloat162_rn(v0, v1);
    uint32_t hb = *(uint32_t*)&h;
    float h0 = __uint_as_float(hb << 16);
    float h1 = __uint_as_float(hb & 0xffff0000u);
    __nv_bfloat162 l = __floats2bfloat162_rn(v0 - h0, v1 - h1);
    hi = hb;
    lo = *(uint32_t*)&l;
}

// ---------------- Prep kernels ----------------
__global__ __launch_bounds__(256) void kern_M(const float* __restrict__ Wsp,
                                              const float* __restrict__ W1) {
    int d = blockIdx.x * 256 + threadIdx.x;
    float m0 = 0.f, m1 = 0.f;
    #pragma unroll 8
    for (int j = 0; j < 64; j++) {
        float w = W1[j * D1_ + d];
        m0 = fmaf(Wsp[j],      w, m0);
        m1 = fmaf(Wsp[64 + j], w, m1);
    }
    g_M[d]       = m0;
    g_M[D1_ + d] = m1;
}

__global__ __launch_bounds__(256) void kern_G(const float* __restrict__ h,
                                              const float* __restrict__ b_sp,
                                              const float* __restrict__ W1,
                                              const float* __restrict__ b1) {
    __shared__ float xs[8][128];
    const int tid  = threadIdx.x;
    const int col  = blockIdx.x * 256 + tid;
    const int row0 = blockIdx.y * 8;
    for (int e = tid; e < 8 * 128; e += 256) {
        int rr = e >> 7, j = e & 127;
        xs[rr][j] = (j < 64) ? b_sp[j] : h[(row0 + rr) * H_ + (j - 64)];
    }
    __syncthreads();
    float acc[8];
    float bb = b1[col];
    #pragma unroll
    for (int r = 0; r < 8; r++) acc[r] = bb;
    #pragma unroll 4
    for (int k = 0; k < 128; k++) {
        float w = W1[k * D1_ + col];
        #pragma unroll
        for (int r = 0; r < 8; r++) acc[r] = fmaf(xs[r][k], w, acc[r]);
    }
    #pragma unroll
    for (int r = 0; r < 8; r++) g_G[(row0 + r) * D1_ + col] = acc[r];
}

__global__ __launch_bounds__(256) void kern_W2T(const float* __restrict__ W2) {
    __shared__ float tile[32][33];
    const int tx = threadIdx.x, ty = threadIdx.y;
    const int n0 = blockIdx.x * 32, k0 = blockIdx.y * 32;
    #pragma unroll
    for (int r = 0; r < 4; r++)
        tile[ty + r * 8][tx] = W2[(k0 + ty + r * 8) * BOT_ + n0 + tx];
    __syncthreads();
    #pragma unroll
    for (int r = 0; r < 4; r++) {
        float v = tile[tx][ty + r * 8];
        __nv_bfloat16 hi = __float2bfloat16(v);
        __nv_bfloat16 lo = __float2bfloat16(v - __bfloat162float(hi));
        int o = (n0 + ty + r * 8) * D1_ + k0 + tx;
        g_W2T_h[o] = hi;
        g_W2T_l[o] = lo;
    }
}

// ---------------- Main kernel ----------------
// Per buffer: Bh 16K | Bl 16K | G 32x288B | M 2x288B  -> 43008 B (1K aligned)
#define OFF_BLO   16384
#define OFF_G     32768
#define OFF_M     41984
#define BUF_STRIDE 43008
#define SMEM_BYTES (2 * BUF_STRIDE)   // 86016

__device__ __forceinline__ void stage_chunk(int k0, uint32_t tb, int t, int n0,
                                            int pedbase) {
    // B hi/lo: 128 n-rows x 8 x 16B (SW128 swizzle on 128B rows)
    #pragma unroll
    for (int i = 0; i < 4; i++) {
        int idx = t + i * 256;
        int n = idx >> 3, seg = idx & 7;
        int sw = n * 128 + ((seg * 16) ^ ((n & 7) << 4));
        const size_t off = (size_t)(n0 + n) * D1_ + k0 + seg * 8;
        CP16(tb + sw, g_W2T_h + off);
        CP16(tb + OFF_BLO + sw, g_W2T_l + off);
    }
    // G: 32 b-rows x 16 x 16B into 288B-stride rows
    #pragma unroll
    for (int i = 0; i < 2; i++) {
        int idx = t + i * 256;
        int b = idx >> 4, seg = idx & 15;
        CP16(tb + OFF_G + b * 288 + seg * 16,
             g_G + (size_t)(pedbase + b) * D1_ + k0 + seg * 4);
    }
    // M: 2 x 64 floats
    if (t < 32) {
        int half = t >> 4, seg = t & 15;
        CP16(tb + OFF_M + half * 288 + seg * 16, g_M + half * D1_ + k0 + seg * 4);
    }
}

__global__ __launch_bounds__(256, 2)
void kern_main_mma(const float* __restrict__ end_pos,
                   const float* __restrict__ b2,
                   float* __restrict__ out) {
    extern __shared__ __align__(1024) char smem[];
    const uint32_t sb = smem_u32(smem);
    const int t = threadIdx.x;
    const int lane = t & 31, wid = t >> 5;
    const int wm = wid >> 1, wn = wid & 1;        // 4 m-warps x 2 n-warps
    const int n0 = blockIdx.x * BN;
    const int r0 = blockIdx.y * BM;
    const int pedbase = (r0 >> 10) << 5;          // scene * 32

    // ---- per-thread rel-pos: warp rows = wm*16..+15; b = (wm&1)*16 + g4 (+8) ----
    const int a_idx = ((blockIdx.y * 2) & 31) + (wm >> 1);
    const float pax = end_pos[(pedbase + a_idx) * 2 + 0];
    const float pay = end_pos[(pedbase + a_idx) * 2 + 1];
    const int g4 = lane >> 2;
    const int b0r = (wm & 1) * 16 + g4;
    const int b1r = b0r + 8;
    float rx0, ry0, rx1, ry1;
    {
        float px = end_pos[(pedbase + b0r) * 2 + 0], py = end_pos[(pedbase + b0r) * 2 + 1];
        rx0 = fminf(fmaxf(px - pax, -1.f), 1.f);
        ry0 = fminf(fmaxf(py - pay, -1.f), 1.f);
        px = end_pos[(pedbase + b1r) * 2 + 0]; py = end_pos[(pedbase + b1r) * 2 + 1];
        rx1 = fminf(fmaxf(px - pax, -1.f), 1.f);
        ry1 = fminf(fmaxf(py - pay, -1.f), 1.f);
    }
    const uint32_t gOff0 = OFF_G + b0r * 288;
    const uint32_t gOff1 = OFF_G + b1r * 288;

    // B ldmatrix lane addressing (col-major frags over warp's 64 n-cols)
    const int bRow   = wn * 64 + (lane & 7) + ((lane >> 4) & 1) * 8;
    const int bKhalf = (lane >> 3) & 1;
    const int kq2    = (lane & 3) * 2;           // A-fragment k pair base

    float c[8][4];
    #pragma unroll
    for (int nt = 0; nt < 8; nt++)
        #pragma unroll
        for (int q = 0; q < 4; q++) c[nt][q] = 0.f;

    // prologue
    stage_chunk(0, sb, t, n0, pedbase);
    CP_COMMIT(); CP_WAIT0();
    __syncthreads();

    for (int ch = 0; ch < NCHUNK; ch++) {
        const int buf = ch & 1;
        const uint32_t tb = sb + buf * BUF_STRIDE;

        if (ch + 1 < NCHUNK) {
            stage_chunk((ch + 1) * BK, sb + (buf ^ 1) * BUF_STRIDE, t, n0, pedbase);
            CP_COMMIT();
        }

        #pragma unroll
        for (int s = 0; s < 4; s++) {
            const int kk = s * 16 + kq2;          // local k (floats) 0..63
            // M pairs
            float2 m0a = lds_f2(tb + OFF_M + kk * 4);
            float2 m0b = lds_f2(tb + OFF_M + kk * 4 + 32);
            float2 m1a = lds_f2(tb + OFF_M + 288 + kk * 4);
            float2 m1b = lds_f2(tb + OFF_M + 288 + kk * 4 + 32);

            // B fragments (hi/lo)
            uint32_t bh[4][4], bl[4][4];
            const int kbB = s * 32 + bKhalf * 16;
            #pragma unroll
            for (int p = 0; p < 4; p++) {
                int row = bRow + p * 16;
                uint32_t bd = tb + row * 128 + (kbB ^ ((row & 7) << 4));
                ldsm4(bh[p], bd);
                ldsm4(bl[p], bd + OFF_BLO);
            }

            // A fragments built in registers
            float2 g0a = lds_f2(tb + gOff0 + kk * 4);
            float2 g1a = lds_f2(tb + gOff1 + kk * 4);
            float2 g0b = lds_f2(tb + gOff0 + kk * 4 + 32);
            float2 g1b = lds_f2(tb + gOff1 + kk * 4 + 32);
            uint32_t ah[4], al[4];
            mk_frag(m0a, m1a, g0a, rx0, ry0, ah[0], al[0]);
            mk_frag(m0a, m1a, g1a, rx1, ry1, ah[1], al[1]);
            mk_frag(m0b, m1b, g0b, rx0, ry0, ah[2], al[2]);
            mk_frag(m0b, m1b, g1b, rx1, ry1, ah[3], al[3]);

            #pragma unroll
            for (int nt = 0; nt < 8; nt++) {
                const uint32_t* BH = &bh[nt >> 1][(nt & 1) * 2];
                const uint32_t* BL = &bl[nt >> 1][(nt & 1) * 2];
                mma16816(c[nt], ah, BH);
                mma16816(c[nt], ah, BL);
                mma16816(c[nt], al, BH);
            }
        }

        if (ch + 1 < NCHUNK) {
            CP_WAIT0();
            __syncthreads();
        }
    }

    // ---- epilogue ----
    // warp-local max over its 16 b-rows, then cross-warp pair (wm, wm^1) via smem
    float* red = (float*)smem;          // [4][128] floats, reuses buffer 0
    #pragma unroll
    for (int nt = 0; nt < 8; nt++) {
        #pragma unroll
        for (int j = 0; j < 2; j++) {
            float m = fmaxf(c[nt][j], c[nt][j + 2]);
            m = fmaxf(m, __shfl_xor_sync(0xffffffffu, m, 4));
            m = fmaxf(m, __shfl_xor_sync(0xffffffffu, m, 8));
            m = fmaxf(m, __shfl_xor_sync(0xffffffffu, m, 16));
            if (lane < 4)
                red[wm * 128 + wn * 64 + nt * 8 + lane * 2 + j] = m;
        }
    }
    __syncthreads();
    {
        const int a_local = t >> 7;          // 0..1
        const int col = t & 127;
        float m = fmaxf(red[(a_local * 2) * 128 + col],
                        red[(a_local * 2 + 1) * 128 + col]);
        const int ped = blockIdx.y * 2 + a_local;
        const int n = n0 + col;
        out[(size_t)ped * BOT_ + n] = fmaxf(m + b2[n], 0.f);
    }
}

// ---------------------------------------------------------------------------
extern "C" void kernel_launch(void* const* d_in, const int* in_sizes, int n_in,
                              void* d_out, int out_size) {
    const float* h_states = (const float*)d_in[0];
    const float* end_pos  = (const float*)d_in[1];
    const float* W_sp = (const float*)d_in[4];
    const float* b_sp = (const float*)d_in[5];
    const float* W1   = (const float*)d_in[6];
    const float* b1   = (const float*)d_in[7];
    const float* W2   = (const float*)d_in[8];
    const float* b2   = (const float*)d_in[9];
    float* out = (float*)d_out;

    cudaFuncSetAttribute(kern_main_mma, cudaFuncAttributeMaxDynamicSharedMemorySize, SMEM_BYTES);

    kern_M<<<D1_ / 256, 256>>>(W_sp, W1);
    kern_G<<<dim3(D1_ / 256, B_ / 8), 256>>>(h_states, b_sp, W1, b1);
    kern_W2T<<<dim3(BOT_ / 32, D1_ / 32), dim3(32, 8)>>>(W2);
    kern_main_mma<<<dim3(BOT_ / BN, RTOT / BM), 256, SMEM_BYTES>>>(end_pos, b2, out);
}